// round 14
// baseline (speedup 1.0000x reference)
#include <cuda_runtime.h>
#include <cstdint>

// ---------------------------------------------------------------------------
// Sinkhorn-Knopp, 65536 independent 32x32 fp32 matrices, 10 iterations.
//
// diag-scaling: iterate only u, v; updates simplified (eps negligible since
// sums are Theta(1)):  u = 1/d ,  v = 1/c  -- single RCP each.
//
// One warp per matrix, 8x4 lane grid: a = lane>>2 (rows 4a..4a+3),
// b = lane&3 (cols 8b..8b+7), g = a>>1. xor-slot REGISTER layout:
//   row slot r      <-> actual row       4a + (b^r)
//   col pair slot k <-> actual col pair  g^k of group b (cols 8b+2(g^k),+1)
// All cross-lane comm is SEL-free shfl_xor (20 SASS SHFL/iter = proven data
// floor). v carried as f32x2 pair replicated across duo lanes.
//
// Global I/O perfectly flat. Input bridges flat->slot through a per-warp
// padded smem tile (stride 36, conflict-free 128-bit ops). Epilogue reads
// the still-flat exp(M0) tile + tiny u,v boards from smem. Final iteration
// is PEELED (no v-allgather, no loop-guard branch in the hot loop).
// ---------------------------------------------------------------------------

#define FMA2(d, a, b, c) \
    asm("fma.rn.f32x2 %0, %1, %2, %3;" : "=l"(d) : "l"(a), "l"(b), "l"(c))
#define MUL2(d, a, b) \
    asm("mul.rn.f32x2 %0, %1, %2;" : "=l"(d) : "l"(a), "l"(b))
#define ADD2(d, a, b) \
    asm("add.rn.f32x2 %0, %1, %2;" : "=l"(d) : "l"(a), "l"(b))
#define PACK2(d, lo, hi) \
    asm("mov.b64 %0, {%1, %2};" : "=l"(d) : "f"(lo), "f"(hi))
#define UNPACK2(lo, hi, s) \
    asm("mov.b64 {%0, %1}, %2;" : "=f"(lo), "=f"(hi) : "l"(s))
#define RCPA(d, s) \
    asm("rcp.approx.f32 %0, %1;" : "=f"(d) : "f"(s))
#define EX2A(d, s) \
    asm("ex2.approx.f32 %0, %1;" : "=f"(d) : "f"(s))

using ull = unsigned long long;

static constexpr float    EPS   = 1e-8f;
static constexpr float    SCALE = 14.4269504088896340736f;  // 10 * log2(e)
static constexpr int      WPB   = 8;                        // warps per block
static constexpr int      SROW  = 36;                       // smem row stride
static constexpr unsigned FULL  = 0xFFFFFFFFu;

__device__ __forceinline__ ull shfl_xor64(ull x, int mask) {
    return __shfl_xor_sync(FULL, x, mask);   // 2 SASS SHFLs
}

struct SKState {
    ull M[4][4];
    ull V[4];
    ull U2[4];
};

// One full row step + col step. Returns u (scalar) and v-pair (vx,vy)
// replicated across duo lanes; updates U2. Does NOT do the v-allgather.
__device__ __forceinline__ void sk_iter_core(SKState& st, int al,
                                             float& u, float& vx, float& vy) {
    // ===== Row step: d = M0 v ; u = 1/d =====
    float D0, D1, D2, D3;
    {
        ull acc;
        MUL2(acc, st.M[0][0], st.V[0]); FMA2(acc, st.M[0][1], st.V[1], acc);
        FMA2(acc, st.M[0][2], st.V[2], acc); FMA2(acc, st.M[0][3], st.V[3], acc);
        float x, y; UNPACK2(x, y, acc); D0 = x + y;
        MUL2(acc, st.M[1][0], st.V[0]); FMA2(acc, st.M[1][1], st.V[1], acc);
        FMA2(acc, st.M[1][2], st.V[2], acc); FMA2(acc, st.M[1][3], st.V[3], acc);
        UNPACK2(x, y, acc); D1 = x + y;
        MUL2(acc, st.M[2][0], st.V[0]); FMA2(acc, st.M[2][1], st.V[1], acc);
        FMA2(acc, st.M[2][2], st.V[2], acc); FMA2(acc, st.M[2][3], st.V[3], acc);
        UNPACK2(x, y, acc); D2 = x + y;
        MUL2(acc, st.M[3][0], st.V[0]); FMA2(acc, st.M[3][1], st.V[1], acc);
        FMA2(acc, st.M[3][2], st.V[2], acc); FMA2(acc, st.M[3][3], st.V[3], acc);
        UNPACK2(x, y, acc); D3 = x + y;
    }
    // xor-slot reduce over b-quad
    D0 += __shfl_xor_sync(FULL, D2, 2);
    D1 += __shfl_xor_sync(FULL, D3, 2);
    D0 += __shfl_xor_sync(FULL, D1, 1);          // full d[4a+b]
    RCPA(u, D0);                                 // u = 1/d
    // u allgather into row slots
    {
        float u1 = __shfl_xor_sync(FULL, u, 1);
        float u2 = __shfl_xor_sync(FULL, u, 2);
        float u3 = __shfl_xor_sync(FULL, u, 3);
        PACK2(st.U2[0], u,  u ); PACK2(st.U2[1], u1, u1);
        PACK2(st.U2[2], u2, u2); PACK2(st.U2[3], u3, u3);
    }

    // ===== Col step: c = M0^T u ; v = 1/c  (dual accumulators) =====
    ull C0, C1, C2, C3, B0, B1, B2, B3;
    MUL2(C0, st.M[0][0], st.U2[0]); FMA2(C0, st.M[1][0], st.U2[1], C0);
    MUL2(B0, st.M[2][0], st.U2[2]); FMA2(B0, st.M[3][0], st.U2[3], B0);
    MUL2(C1, st.M[0][1], st.U2[0]); FMA2(C1, st.M[1][1], st.U2[1], C1);
    MUL2(B1, st.M[2][1], st.U2[2]); FMA2(B1, st.M[3][1], st.U2[3], B1);
    MUL2(C2, st.M[0][2], st.U2[0]); FMA2(C2, st.M[1][2], st.U2[1], C2);
    MUL2(B2, st.M[2][2], st.U2[2]); FMA2(B2, st.M[3][2], st.U2[3], B2);
    MUL2(C3, st.M[0][3], st.U2[0]); FMA2(C3, st.M[1][3], st.U2[1], C3);
    MUL2(B3, st.M[2][3], st.U2[2]); FMA2(B3, st.M[3][3], st.U2[3], B3);
    ADD2(C0, C0, B0); ADD2(C1, C1, B1);
    ADD2(C2, C2, B2); ADD2(C3, C3, B3);
    // xor-slot reduce over the 8 a-lanes (pair payloads, duo-complete)
    {
        ull t;
        t = shfl_xor64(C2, 16); ADD2(C0, C0, t);
        t = shfl_xor64(C3, 16); ADD2(C1, C1, t);
        t = shfl_xor64(C1, 8);  ADD2(C0, C0, t);
        t = shfl_xor64(C0, 4);  ADD2(C0, C0, t);  // full pair on duo
    }
    // v-pair update (replicated across duo; no routing selects)
    float cx, cy; UNPACK2(cx, cy, C0);
    RCPA(vx, cx); RCPA(vy, cy);
    (void)al;
}

__global__ __launch_bounds__(WPB * 32, 4)
void sinkhorn_kernel(const float* __restrict__ H,
                     float* __restrict__ Out,
                     int nmat) {
    // per-warp: 32x32 padded tile + u[32] + v[32]
    __shared__ __align__(16) float S[WPB][32 * SROW + 64];

    const int lane = threadIdx.x & 31;
    const int wid  = threadIdx.x >> 5;
    const int a    = lane >> 2;      // 0..7 (rows 4a..4a+3)
    const int b    = lane & 3;       // 0..3 (cols 8b..8b+7)
    const int g    = a >> 1;         // 0..3 (own col-pair index in group)
    const int al   = a & 1;          // element within own col pair
    const int g0   = g & 1;          // pair-swap bit
    const int g1   = g >> 1;         // chunk-select bit

    const int m = blockIdx.x * WPB + wid;
    if (m >= nmat) return;           // warp-uniform

    float* s  = S[wid];
    float* su = S[wid] + 32 * SROW;        // u[32]
    float* sv = S[wid] + 32 * SROW + 32;   // v[32]
    const float4* src = reinterpret_cast<const float4*>(H)  + (size_t)m * 256;
    float4*       dst = reinterpret_cast<float4*>(Out)      + (size_t)m * 256;

    ull SC2;  PACK2(SC2, SCALE, SCALE);
    ull ONE2; PACK2(ONE2, 1.0f, 1.0f);

    // ---- Flat load (4 lines/inst), scale+exp+clamp, flat STS.128 ----
#pragma unroll
    for (int k = 0; k < 8; k++) {
        const int f = k * 32 + lane;            // float4 index in matrix
        float4 q = src[f];
        ull p0, p1;
        PACK2(p0, q.x, q.y);
        PACK2(p1, q.z, q.w);
        MUL2(p0, p0, SC2);
        MUL2(p1, p1, SC2);
        float x0, y0, x1, y1;
        UNPACK2(x0, y0, p0); UNPACK2(x1, y1, p1);
        EX2A(x0, x0); EX2A(y0, y0); EX2A(x1, x1); EX2A(y1, y1);
        q.x = fmaxf(x0, EPS); q.y = fmaxf(y0, EPS);
        q.z = fmaxf(x1, EPS); q.w = fmaxf(y1, EPS);
        const int row = f >> 3;                 // 8 float4 per row
        const int ch  = f & 7;
        *reinterpret_cast<float4*>(s + row * SROW + ch * 4) = q;
    }
    __syncwarp();

    // ---- Gather xor-slot registers via conflict-free LDS.128 ----
    SKState st;
#pragma unroll
    for (int r = 0; r < 4; r++) {
        const int R = 4 * a + (b ^ r);
#pragma unroll
        for (int T = 0; T < 2; T++) {
            const int Q = 2 * b + (g1 ^ T);
            const ulonglong2 q =
                *reinterpret_cast<const ulonglong2*>(s + R * SROW + 4 * Q);
            st.M[r][2 * T]     = g0 ? q.y : q.x;
            st.M[r][2 * T + 1] = g0 ? q.x : q.y;
        }
    }

    st.V[0] = ONE2; st.V[1] = ONE2; st.V[2] = ONE2; st.V[3] = ONE2;

    // ---- 9 full iterations (with v-allgather) ----
#pragma unroll 1
    for (int it = 0; it < 9; it++) {
        float u, vx, vy;
        sk_iter_core(st, al, u, vx, vy);
        // v allgather into col-pair slots
        PACK2(st.V[0], vx, vy);                  // own pair g
        st.V[1] = shfl_xor64(st.V[0], 8);
        st.V[2] = shfl_xor64(st.V[0], 16);
        st.V[3] = shfl_xor64(st.V[0], 24);
    }

    // ---- Peeled final iteration: no v-allgather, write u,v boards ----
    {
        float u, vx, vy;
        sk_iter_core(st, al, u, vx, vy);
        su[4 * a + b] = u;                       // u[row 4a+b]
        if (al == 0) {                           // one duo lane stores v pair
            sv[8 * b + 2 * g]     = vx;
            sv[8 * b + 2 * g + 1] = vy;
        }
    }
    __syncwarp();

    // ---- Epilogue: out[i][j] = u_i * exp(M0)[i][j] * v_j ----
    // Tile still holds flat exp(M0). Row remap: lane covers rows
    // ro*8 .. ro*8+7 (ro = lane>>3), its 8 u's contiguous in smem.
    const int ch = lane & 7;                    // fixed chunk (cols 4ch..4ch+3)
    const int ro = lane >> 3;                   // octet -> row group
    const ulonglong2 vq =
        *reinterpret_cast<const ulonglong2*>(sv + 4 * ch);   // v pairs
    const float4 ua = *reinterpret_cast<const float4*>(su + ro * 8);
    const float4 ub = *reinterpret_cast<const float4*>(su + ro * 8 + 4);
#pragma unroll
    for (int k = 0; k < 8; k++) {
        const int row = ro * 8 + k;
        const float uu = (k < 4)
            ? ((k & 2) ? ((k & 1) ? ua.w : ua.z) : ((k & 1) ? ua.y : ua.x))
            : ((k & 2) ? ((k & 1) ? ub.w : ub.z) : ((k & 1) ? ub.y : ub.x));
        ull ud; PACK2(ud, uu, uu);
        const ulonglong2 mq =
            *reinterpret_cast<const ulonglong2*>(s + row * SROW + ch * 4);
        ull o0, o1;
        MUL2(o0, mq.x, vq.x); MUL2(o0, o0, ud);
        MUL2(o1, mq.y, vq.y); MUL2(o1, o1, ud);
        float4 t;
        UNPACK2(t.x, t.y, o0);
        UNPACK2(t.z, t.w, o1);
        dst[row * 8 + ch] = t;
    }
}

extern "C" void kernel_launch(void* const* d_in, const int* in_sizes, int n_in,
                              void* d_out, int out_size) {
    const float* H   = (const float*)d_in[0];
    float*       out = (float*)d_out;
    const int nmat   = in_sizes[0] / 1024;          // 32*32 per matrix
    const int blocks = (nmat + WPB - 1) / WPB;
    sinkhorn_kernel<<<blocks, WPB * 32>>>(H, out, nmat);
}

// round 15
// speedup vs baseline: 1.0285x; 1.0285x over previous
#include <cuda_runtime.h>
#include <cstdint>

// ---------------------------------------------------------------------------
// Sinkhorn-Knopp, 65536 independent 32x32 fp32 matrices, 10 iterations.
//
// diag-scaling: iterate only u, v; updates simplified (eps negligible since
// sums are Theta(1)):  u = 1/d ,  v = 1/c  -- single RCP each.
//
// One warp per matrix, 8x4 lane grid: a = lane>>2 (rows 4a..4a+3),
// b = lane&3 (cols 8b..8b+7), g = a>>1. xor-slot REGISTER layout:
//   row slot r      <-> actual row       4a + (b^r)
//   col pair slot k <-> actual col pair  g^k of group b (cols 8b+2(g^k),+1)
// All cross-lane comm is SEL-free shfl_xor (20 SASS SHFL/iter = proven data
// floor). v carried as f32x2 pair replicated across duo lanes.
//
// Global I/O perfectly flat. Input bridges flat->slot through a per-warp
// padded smem tile (stride 36, conflict-free 128-bit ops). Epilogue reads
// the still-flat exp(M0) tile + tiny u,v boards from smem. Final iteration
// is PEELED (no loop-guard branch in the hot loop; no v-allgather at end).
// Block shape stays at the proven WPB=4 / 128 threads.
// ---------------------------------------------------------------------------

#define FMA2(d, a, b, c) \
    asm("fma.rn.f32x2 %0, %1, %2, %3;" : "=l"(d) : "l"(a), "l"(b), "l"(c))
#define MUL2(d, a, b) \
    asm("mul.rn.f32x2 %0, %1, %2;" : "=l"(d) : "l"(a), "l"(b))
#define ADD2(d, a, b) \
    asm("add.rn.f32x2 %0, %1, %2;" : "=l"(d) : "l"(a), "l"(b))
#define PACK2(d, lo, hi) \
    asm("mov.b64 %0, {%1, %2};" : "=l"(d) : "f"(lo), "f"(hi))
#define UNPACK2(lo, hi, s) \
    asm("mov.b64 {%0, %1}, %2;" : "=f"(lo), "=f"(hi) : "l"(s))
#define RCPA(d, s) \
    asm("rcp.approx.f32 %0, %1;" : "=f"(d) : "f"(s))
#define EX2A(d, s) \
    asm("ex2.approx.f32 %0, %1;" : "=f"(d) : "f"(s))

using ull = unsigned long long;

static constexpr float    EPS   = 1e-8f;
static constexpr float    SCALE = 14.4269504088896340736f;  // 10 * log2(e)
static constexpr int      WPB   = 4;                        // warps per block
static constexpr int      SROW  = 36;                       // smem row stride
static constexpr unsigned FULL  = 0xFFFFFFFFu;

__device__ __forceinline__ ull shfl_xor64(ull x, int mask) {
    return __shfl_xor_sync(FULL, x, mask);   // 2 SASS SHFLs
}

struct SKState {
    ull M[4][4];
    ull V[4];
    ull U2[4];
};

// One full row step + col step. Produces u (scalar, own row 4a+b) and the
// v-pair (vx,vy) replicated across duo lanes; refreshes U2. Does NOT do the
// v-allgather (caller decides).
__device__ __forceinline__ void sk_iter_core(SKState& st,
                                             float& u, float& vx, float& vy) {
    // ===== Row step: d = M0 v ; u = 1/d =====
    float D0, D1, D2, D3;
    {
        ull acc;
        MUL2(acc, st.M[0][0], st.V[0]); FMA2(acc, st.M[0][1], st.V[1], acc);
        FMA2(acc, st.M[0][2], st.V[2], acc); FMA2(acc, st.M[0][3], st.V[3], acc);
        float x, y; UNPACK2(x, y, acc); D0 = x + y;
        MUL2(acc, st.M[1][0], st.V[0]); FMA2(acc, st.M[1][1], st.V[1], acc);
        FMA2(acc, st.M[1][2], st.V[2], acc); FMA2(acc, st.M[1][3], st.V[3], acc);
        UNPACK2(x, y, acc); D1 = x + y;
        MUL2(acc, st.M[2][0], st.V[0]); FMA2(acc, st.M[2][1], st.V[1], acc);
        FMA2(acc, st.M[2][2], st.V[2], acc); FMA2(acc, st.M[2][3], st.V[3], acc);
        UNPACK2(x, y, acc); D2 = x + y;
        MUL2(acc, st.M[3][0], st.V[0]); FMA2(acc, st.M[3][1], st.V[1], acc);
        FMA2(acc, st.M[3][2], st.V[2], acc); FMA2(acc, st.M[3][3], st.V[3], acc);
        UNPACK2(x, y, acc); D3 = x + y;
    }
    // xor-slot reduce over b-quad (slot r on lane b holds row 4a+(b^r))
    D0 += __shfl_xor_sync(FULL, D2, 2);
    D1 += __shfl_xor_sync(FULL, D3, 2);
    D0 += __shfl_xor_sync(FULL, D1, 1);          // full d[4a+b]
    RCPA(u, D0);                                 // u = 1/d
    // u allgather into row slots
    {
        float u1 = __shfl_xor_sync(FULL, u, 1);
        float u2 = __shfl_xor_sync(FULL, u, 2);
        float u3 = __shfl_xor_sync(FULL, u, 3);
        PACK2(st.U2[0], u,  u ); PACK2(st.U2[1], u1, u1);
        PACK2(st.U2[2], u2, u2); PACK2(st.U2[3], u3, u3);
    }

    // ===== Col step: c = M0^T u ; v = 1/c  (dual accumulators) =====
    ull C0, C1, C2, C3, B0, B1, B2, B3;
    MUL2(C0, st.M[0][0], st.U2[0]); FMA2(C0, st.M[1][0], st.U2[1], C0);
    MUL2(B0, st.M[2][0], st.U2[2]); FMA2(B0, st.M[3][0], st.U2[3], B0);
    MUL2(C1, st.M[0][1], st.U2[0]); FMA2(C1, st.M[1][1], st.U2[1], C1);
    MUL2(B1, st.M[2][1], st.U2[2]); FMA2(B1, st.M[3][1], st.U2[3], B1);
    MUL2(C2, st.M[0][2], st.U2[0]); FMA2(C2, st.M[1][2], st.U2[1], C2);
    MUL2(B2, st.M[2][2], st.U2[2]); FMA2(B2, st.M[3][2], st.U2[3], B2);
    MUL2(C3, st.M[0][3], st.U2[0]); FMA2(C3, st.M[1][3], st.U2[1], C3);
    MUL2(B3, st.M[2][3], st.U2[2]); FMA2(B3, st.M[3][3], st.U2[3], B3);
    ADD2(C0, C0, B0); ADD2(C1, C1, B1);
    ADD2(C2, C2, B2); ADD2(C3, C3, B3);
    // xor-slot reduce over the 8 a-lanes (pair payloads, duo-complete)
    {
        ull t;
        t = shfl_xor64(C2, 16); ADD2(C0, C0, t);
        t = shfl_xor64(C3, 16); ADD2(C1, C1, t);
        t = shfl_xor64(C1, 8);  ADD2(C0, C0, t);
        t = shfl_xor64(C0, 4);  ADD2(C0, C0, t);  // full pair on duo
    }
    // v-pair update (replicated across duo; no routing selects)
    float cx, cy; UNPACK2(cx, cy, C0);
    RCPA(vx, cx); RCPA(vy, cy);
}

__global__ __launch_bounds__(WPB * 32, 8)
void sinkhorn_kernel(const float* __restrict__ H,
                     float* __restrict__ Out,
                     int nmat) {
    // per-warp: 32x32 padded tile + u[32] + v[32]
    __shared__ __align__(16) float S[WPB][32 * SROW + 64];

    const int lane = threadIdx.x & 31;
    const int wid  = threadIdx.x >> 5;
    const int a    = lane >> 2;      // 0..7 (rows 4a..4a+3)
    const int b    = lane & 3;       // 0..3 (cols 8b..8b+7)
    const int g    = a >> 1;         // 0..3 (own col-pair index in group)
    const int al   = a & 1;          // element within own col pair
    const int g0   = g & 1;          // pair-swap bit
    const int g1   = g >> 1;         // chunk-select bit

    const int m = blockIdx.x * WPB + wid;
    if (m >= nmat) return;           // warp-uniform

    float* s  = S[wid];
    float* su = S[wid] + 32 * SROW;        // u[32]
    float* sv = S[wid] + 32 * SROW + 32;   // v[32]
    const float4* src = reinterpret_cast<const float4*>(H)  + (size_t)m * 256;
    float4*       dst = reinterpret_cast<float4*>(Out)      + (size_t)m * 256;

    ull SC2;  PACK2(SC2, SCALE, SCALE);
    ull ONE2; PACK2(ONE2, 1.0f, 1.0f);

    // ---- Flat load (4 lines/inst), scale+exp+clamp, flat STS.128 ----
#pragma unroll
    for (int k = 0; k < 8; k++) {
        const int f = k * 32 + lane;            // float4 index in matrix
        float4 q = src[f];
        ull p0, p1;
        PACK2(p0, q.x, q.y);
        PACK2(p1, q.z, q.w);
        MUL2(p0, p0, SC2);
        MUL2(p1, p1, SC2);
        float x0, y0, x1, y1;
        UNPACK2(x0, y0, p0); UNPACK2(x1, y1, p1);
        EX2A(x0, x0); EX2A(y0, y0); EX2A(x1, x1); EX2A(y1, y1);
        q.x = fmaxf(x0, EPS); q.y = fmaxf(y0, EPS);
        q.z = fmaxf(x1, EPS); q.w = fmaxf(y1, EPS);
        const int row = f >> 3;                 // 8 float4 per row
        const int ch  = f & 7;
        *reinterpret_cast<float4*>(s + row * SROW + ch * 4) = q;
    }
    __syncwarp();

    // ---- Gather xor-slot registers via conflict-free LDS.128 ----
    // chunk Q = 2b + (g1^T) holds col pairs 2Q (lo) and 2Q+1 (hi);
    // slot 2T is the one whose pair-bit0 == g0.
    SKState st;
#pragma unroll
    for (int r = 0; r < 4; r++) {
        const int R = 4 * a + (b ^ r);
#pragma unroll
        for (int T = 0; T < 2; T++) {
            const int Q = 2 * b + (g1 ^ T);
            const ulonglong2 q =
                *reinterpret_cast<const ulonglong2*>(s + R * SROW + 4 * Q);
            st.M[r][2 * T]     = g0 ? q.y : q.x;
            st.M[r][2 * T + 1] = g0 ? q.x : q.y;
        }
    }

    st.V[0] = ONE2; st.V[1] = ONE2; st.V[2] = ONE2; st.V[3] = ONE2;

    // ---- 9 full iterations (with v-allgather) ----
#pragma unroll 1
    for (int it = 0; it < 9; it++) {
        float u, vx, vy;
        sk_iter_core(st, u, vx, vy);
        // v allgather into col-pair slots
        PACK2(st.V[0], vx, vy);                  // own pair g
        st.V[1] = shfl_xor64(st.V[0], 8);
        st.V[2] = shfl_xor64(st.V[0], 16);
        st.V[3] = shfl_xor64(st.V[0], 24);
    }

    // ---- Peeled final iteration: no v-allgather, write u,v boards ----
    {
        float u, vx, vy;
        sk_iter_core(st, u, vx, vy);
        su[4 * a + b] = u;                       // u[row 4a+b]
        if (al == 0) {                           // one duo lane stores v pair
            sv[8 * b + 2 * g]     = vx;
            sv[8 * b + 2 * g + 1] = vy;
        }
    }
    __syncwarp();

    // ---- Epilogue: out[i][j] = u_i * exp(M0)[i][j] * v_j ----
    // Tile still holds flat exp(M0). Row remap: lane covers rows
    // ro*8 .. ro*8+7 (ro = lane>>3), its 8 u's contiguous in smem
    // (2 broadcast LDS.128). Global stores remain 4x128B lines per inst.
    const int ch = lane & 7;                    // fixed chunk (cols 4ch..4ch+3)
    const int ro = lane >> 3;                   // octet -> row group
    const ulonglong2 vq =
        *reinterpret_cast<const ulonglong2*>(sv + 4 * ch);   // v pairs
    const float4 ua = *reinterpret_cast<const float4*>(su + ro * 8);
    const float4 ub = *reinterpret_cast<const float4*>(su + ro * 8 + 4);
    const float us[8] = { ua.x, ua.y, ua.z, ua.w, ub.x, ub.y, ub.z, ub.w };
#pragma unroll
    for (int k = 0; k < 8; k++) {
        const int row = ro * 8 + k;
        ull ud; PACK2(ud, us[k], us[k]);
        const ulonglong2 mq =
            *reinterpret_cast<const ulonglong2*>(s + row * SROW + ch * 4);
        ull o0, o1;
        MUL2(o0, mq.x, vq.x); MUL2(o0, o0, ud);
        MUL2(o1, mq.y, vq.y); MUL2(o1, o1, ud);
        float4 t;
        UNPACK2(t.x, t.y, o0);
        UNPACK2(t.z, t.w, o1);
        dst[row * 8 + ch] = t;
    }
}

extern "C" void kernel_launch(void* const* d_in, const int* in_sizes, int n_in,
                              void* d_out, int out_size) {
    const float* H   = (const float*)d_in[0];
    float*       out = (float*)d_out;
    const int nmat   = in_sizes[0] / 1024;          // 32*32 per matrix
    const int blocks = (nmat + WPB - 1) / WPB;
    sinkhorn_kernel<<<blocks, WPB * 32>>>(H, out, nmat);
}

// round 16
// speedup vs baseline: 1.0318x; 1.0032x over previous
#include <cuda_runtime.h>
#include <cstdint>

// ---------------------------------------------------------------------------
// Sinkhorn-Knopp, 65536 independent 32x32 fp32 matrices, 10 iterations.
//
// diag-scaling: iterate only u, v; updates simplified (eps negligible since
// sums are Theta(1)):  u = 1/d ,  v = 1/c  -- single RCP each.
//
// One warp per matrix, 8x4 lane grid: a = lane>>2 (rows 4a..4a+3),
// b = lane&3 (cols 8b..8b+7), g = a>>1. xor-slot REGISTER layout:
//   row slot r      <-> actual row       4a + (b^r)
//   col pair slot k <-> actual col pair  g^k of group b (cols 8b+2(g^k),+1)
// All cross-lane comm is SEL-free shfl_xor (20 SASS SHFL/iter = proven data
// floor). v carried as f32x2 pair replicated across duo lanes.
//
// Global I/O perfectly flat. Input bridges flat->slot through a per-warp
// padded smem tile (stride 36, conflict-free 128-bit ops). Epilogue reads
// the still-flat exp(M0) tile + tiny u,v boards from smem. Final iteration
// peeled. Main loop unrolled x3 so ptxas can overlap adjacent iterations'
// FMA work into the SHFL/RCP latency shadows (sole change this round).
// ---------------------------------------------------------------------------

#define FMA2(d, a, b, c) \
    asm("fma.rn.f32x2 %0, %1, %2, %3;" : "=l"(d) : "l"(a), "l"(b), "l"(c))
#define MUL2(d, a, b) \
    asm("mul.rn.f32x2 %0, %1, %2;" : "=l"(d) : "l"(a), "l"(b))
#define ADD2(d, a, b) \
    asm("add.rn.f32x2 %0, %1, %2;" : "=l"(d) : "l"(a), "l"(b))
#define PACK2(d, lo, hi) \
    asm("mov.b64 %0, {%1, %2};" : "=l"(d) : "f"(lo), "f"(hi))
#define UNPACK2(lo, hi, s) \
    asm("mov.b64 {%0, %1}, %2;" : "=f"(lo), "=f"(hi) : "l"(s))
#define RCPA(d, s) \
    asm("rcp.approx.f32 %0, %1;" : "=f"(d) : "f"(s))
#define EX2A(d, s) \
    asm("ex2.approx.f32 %0, %1;" : "=f"(d) : "f"(s))

using ull = unsigned long long;

static constexpr float    EPS   = 1e-8f;
static constexpr float    SCALE = 14.4269504088896340736f;  // 10 * log2(e)
static constexpr int      WPB   = 4;                        // warps per block
static constexpr int      SROW  = 36;                       // smem row stride
static constexpr unsigned FULL  = 0xFFFFFFFFu;

__device__ __forceinline__ ull shfl_xor64(ull x, int mask) {
    return __shfl_xor_sync(FULL, x, mask);   // 2 SASS SHFLs
}

struct SKState {
    ull M[4][4];
    ull V[4];
    ull U2[4];
};

// One full row step + col step. Produces u (scalar, own row 4a+b) and the
// v-pair (vx,vy) replicated across duo lanes; refreshes U2. Does NOT do the
// v-allgather (caller decides).
__device__ __forceinline__ void sk_iter_core(SKState& st,
                                             float& u, float& vx, float& vy) {
    // ===== Row step: d = M0 v ; u = 1/d =====
    float D0, D1, D2, D3;
    {
        ull acc;
        MUL2(acc, st.M[0][0], st.V[0]); FMA2(acc, st.M[0][1], st.V[1], acc);
        FMA2(acc, st.M[0][2], st.V[2], acc); FMA2(acc, st.M[0][3], st.V[3], acc);
        float x, y; UNPACK2(x, y, acc); D0 = x + y;
        MUL2(acc, st.M[1][0], st.V[0]); FMA2(acc, st.M[1][1], st.V[1], acc);
        FMA2(acc, st.M[1][2], st.V[2], acc); FMA2(acc, st.M[1][3], st.V[3], acc);
        UNPACK2(x, y, acc); D1 = x + y;
        MUL2(acc, st.M[2][0], st.V[0]); FMA2(acc, st.M[2][1], st.V[1], acc);
        FMA2(acc, st.M[2][2], st.V[2], acc); FMA2(acc, st.M[2][3], st.V[3], acc);
        UNPACK2(x, y, acc); D2 = x + y;
        MUL2(acc, st.M[3][0], st.V[0]); FMA2(acc, st.M[3][1], st.V[1], acc);
        FMA2(acc, st.M[3][2], st.V[2], acc); FMA2(acc, st.M[3][3], st.V[3], acc);
        UNPACK2(x, y, acc); D3 = x + y;
    }
    // xor-slot reduce over b-quad (slot r on lane b holds row 4a+(b^r))
    D0 += __shfl_xor_sync(FULL, D2, 2);
    D1 += __shfl_xor_sync(FULL, D3, 2);
    D0 += __shfl_xor_sync(FULL, D1, 1);          // full d[4a+b]
    RCPA(u, D0);                                 // u = 1/d
    // u allgather into row slots
    {
        float u1 = __shfl_xor_sync(FULL, u, 1);
        float u2 = __shfl_xor_sync(FULL, u, 2);
        float u3 = __shfl_xor_sync(FULL, u, 3);
        PACK2(st.U2[0], u,  u ); PACK2(st.U2[1], u1, u1);
        PACK2(st.U2[2], u2, u2); PACK2(st.U2[3], u3, u3);
    }

    // ===== Col step: c = M0^T u ; v = 1/c  (dual accumulators) =====
    ull C0, C1, C2, C3, B0, B1, B2, B3;
    MUL2(C0, st.M[0][0], st.U2[0]); FMA2(C0, st.M[1][0], st.U2[1], C0);
    MUL2(B0, st.M[2][0], st.U2[2]); FMA2(B0, st.M[3][0], st.U2[3], B0);
    MUL2(C1, st.M[0][1], st.U2[0]); FMA2(C1, st.M[1][1], st.U2[1], C1);
    MUL2(B1, st.M[2][1], st.U2[2]); FMA2(B1, st.M[3][1], st.U2[3], B1);
    MUL2(C2, st.M[0][2], st.U2[0]); FMA2(C2, st.M[1][2], st.U2[1], C2);
    MUL2(B2, st.M[2][2], st.U2[2]); FMA2(B2, st.M[3][2], st.U2[3], B2);
    MUL2(C3, st.M[0][3], st.U2[0]); FMA2(C3, st.M[1][3], st.U2[1], C3);
    MUL2(B3, st.M[2][3], st.U2[2]); FMA2(B3, st.M[3][3], st.U2[3], B3);
    ADD2(C0, C0, B0); ADD2(C1, C1, B1);
    ADD2(C2, C2, B2); ADD2(C3, C3, B3);
    // xor-slot reduce over the 8 a-lanes (pair payloads, duo-complete)
    {
        ull t;
        t = shfl_xor64(C2, 16); ADD2(C0, C0, t);
        t = shfl_xor64(C3, 16); ADD2(C1, C1, t);
        t = shfl_xor64(C1, 8);  ADD2(C0, C0, t);
        t = shfl_xor64(C0, 4);  ADD2(C0, C0, t);  // full pair on duo
    }
    // v-pair update (replicated across duo; no routing selects)
    float cx, cy; UNPACK2(cx, cy, C0);
    RCPA(vx, cx); RCPA(vy, cy);
}

__global__ __launch_bounds__(WPB * 32, 8)
void sinkhorn_kernel(const float* __restrict__ H,
                     float* __restrict__ Out,
                     int nmat) {
    // per-warp: 32x32 padded tile + u[32] + v[32]
    __shared__ __align__(16) float S[WPB][32 * SROW + 64];

    const int lane = threadIdx.x & 31;
    const int wid  = threadIdx.x >> 5;
    const int a    = lane >> 2;      // 0..7 (rows 4a..4a+3)
    const int b    = lane & 3;       // 0..3 (cols 8b..8b+7)
    const int g    = a >> 1;         // 0..3 (own col-pair index in group)
    const int al   = a & 1;          // element within own col pair
    const int g0   = g & 1;          // pair-swap bit
    const int g1   = g >> 1;         // chunk-select bit

    const int m = blockIdx.x * WPB + wid;
    if (m >= nmat) return;           // warp-uniform

    float* s  = S[wid];
    float* su = S[wid] + 32 * SROW;        // u[32]
    float* sv = S[wid] + 32 * SROW + 32;   // v[32]
    const float4* src = reinterpret_cast<const float4*>(H)  + (size_t)m * 256;
    float4*       dst = reinterpret_cast<float4*>(Out)      + (size_t)m * 256;

    ull SC2;  PACK2(SC2, SCALE, SCALE);
    ull ONE2; PACK2(ONE2, 1.0f, 1.0f);

    // ---- Flat load (4 lines/inst), scale+exp+clamp, flat STS.128 ----
#pragma unroll
    for (int k = 0; k < 8; k++) {
        const int f = k * 32 + lane;            // float4 index in matrix
        float4 q = src[f];
        ull p0, p1;
        PACK2(p0, q.x, q.y);
        PACK2(p1, q.z, q.w);
        MUL2(p0, p0, SC2);
        MUL2(p1, p1, SC2);
        float x0, y0, x1, y1;
        UNPACK2(x0, y0, p0); UNPACK2(x1, y1, p1);
        EX2A(x0, x0); EX2A(y0, y0); EX2A(x1, x1); EX2A(y1, y1);
        q.x = fmaxf(x0, EPS); q.y = fmaxf(y0, EPS);
        q.z = fmaxf(x1, EPS); q.w = fmaxf(y1, EPS);
        const int row = f >> 3;                 // 8 float4 per row
        const int ch  = f & 7;
        *reinterpret_cast<float4*>(s + row * SROW + ch * 4) = q;
    }
    __syncwarp();

    // ---- Gather xor-slot registers via conflict-free LDS.128 ----
    // chunk Q = 2b + (g1^T) holds col pairs 2Q (lo) and 2Q+1 (hi);
    // slot 2T is the one whose pair-bit0 == g0.
    SKState st;
#pragma unroll
    for (int r = 0; r < 4; r++) {
        const int R = 4 * a + (b ^ r);
#pragma unroll
        for (int T = 0; T < 2; T++) {
            const int Q = 2 * b + (g1 ^ T);
            const ulonglong2 q =
                *reinterpret_cast<const ulonglong2*>(s + R * SROW + 4 * Q);
            st.M[r][2 * T]     = g0 ? q.y : q.x;
            st.M[r][2 * T + 1] = g0 ? q.x : q.y;
        }
    }

    st.V[0] = ONE2; st.V[1] = ONE2; st.V[2] = ONE2; st.V[3] = ONE2;

    // ---- 9 full iterations (with v-allgather), unrolled x3 so ptxas can
    // overlap adjacent iterations' independent work into SHFL/RCP stalls ----
#pragma unroll 3
    for (int it = 0; it < 9; it++) {
        float u, vx, vy;
        sk_iter_core(st, u, vx, vy);
        // v allgather into col-pair slots
        PACK2(st.V[0], vx, vy);                  // own pair g
        st.V[1] = shfl_xor64(st.V[0], 8);
        st.V[2] = shfl_xor64(st.V[0], 16);
        st.V[3] = shfl_xor64(st.V[0], 24);
    }

    // ---- Peeled final iteration: no v-allgather, write u,v boards ----
    {
        float u, vx, vy;
        sk_iter_core(st, u, vx, vy);
        su[4 * a + b] = u;                       // u[row 4a+b]
        if (al == 0) {                           // one duo lane stores v pair
            sv[8 * b + 2 * g]     = vx;
            sv[8 * b + 2 * g + 1] = vy;
        }
    }
    __syncwarp();

    // ---- Epilogue: out[i][j] = u_i * exp(M0)[i][j] * v_j ----
    // Tile still holds flat exp(M0). Row remap: lane covers rows
    // ro*8 .. ro*8+7 (ro = lane>>3), its 8 u's contiguous in smem
    // (2 broadcast LDS.128). Global stores remain 4x128B lines per inst.
    const int ch = lane & 7;                    // fixed chunk (cols 4ch..4ch+3)
    const int ro = lane >> 3;                   // octet -> row group
    const ulonglong2 vq =
        *reinterpret_cast<const ulonglong2*>(sv + 4 * ch);   // v pairs
    const float4 ua = *reinterpret_cast<const float4*>(su + ro * 8);
    const float4 ub = *reinterpret_cast<const float4*>(su + ro * 8 + 4);
    const float us[8] = { ua.x, ua.y, ua.z, ua.w, ub.x, ub.y, ub.z, ub.w };
#pragma unroll
    for (int k = 0; k < 8; k++) {
        const int row = ro * 8 + k;
        ull ud; PACK2(ud, us[k], us[k]);
        const ulonglong2 mq =
            *reinterpret_cast<const ulonglong2*>(s + row * SROW + ch * 4);
        ull o0, o1;
        MUL2(o0, mq.x, vq.x); MUL2(o0, o0, ud);
        MUL2(o1, mq.y, vq.y); MUL2(o1, o1, ud);
        float4 t;
        UNPACK2(t.x, t.y, o0);
        UNPACK2(t.z, t.w, o1);
        dst[row * 8 + ch] = t;
    }
}

extern "C" void kernel_launch(void* const* d_in, const int* in_sizes, int n_in,
                              void* d_out, int out_size) {
    const float* H   = (const float*)d_in[0];
    float*       out = (float*)d_out;
    const int nmat   = in_sizes[0] / 1024;          // 32*32 per matrix
    const int blocks = (nmat + WPB - 1) / WPB;
    sinkhorn_kernel<<<blocks, WPB * 32>>>(H, out, nmat);
}

// round 17
// speedup vs baseline: 1.0343x; 1.0024x over previous
#include <cuda_runtime.h>
#include <cstdint>

// ---------------------------------------------------------------------------
// Sinkhorn-Knopp, 65536 independent 32x32 fp32 matrices, 10 iterations.
//
// diag-scaling: iterate only u, v; updates simplified (eps negligible since
// sums are Theta(1)):  u = 1/d ,  v = 1/c  -- single RCP each.
//
// One warp per matrix, 8x4 lane grid: a = lane>>2 (rows 4a..4a+3),
// b = lane&3 (cols 8b..8b+7), g = a>>1. xor-slot REGISTER layout:
//   row slot r      <-> actual row       4a + (b^r)
//   col pair slot k <-> actual col pair  g^k of group b (cols 8b+2(g^k),+1)
// All cross-lane comm is SEL-free shfl_xor (20 SASS SHFL/iter = proven data
// floor). v carried as f32x2 pair replicated across duo lanes.
//
// Global I/O perfectly flat. Input bridges flat->slot through a per-warp
// padded smem tile (stride 36, conflict-free 128-bit ops). Epilogue reads
// the still-flat exp(M0) tile + tiny u,v boards from smem. Final iteration
// peeled. THIS ROUND: pack/unpack of f32x2 halves expressed as union bit-
// casts (not asm movs) so ptxas can coalesce register pairs and delete MOVs.
// ---------------------------------------------------------------------------

using ull = unsigned long long;

union F2U { ull u; float2 f; };

// Compiler-visible pack/unpack (ptxas can alias the register pair).
#define PACK2(d, lo, hi) do { F2U _t; _t.f.x = (lo); _t.f.y = (hi); (d) = _t.u; } while (0)
#define UNPACK2(lo, hi, s) do { F2U _t; _t.u = (s); (lo) = _t.f.x; (hi) = _t.f.y; } while (0)

#define FMA2(d, a, b, c) \
    asm("fma.rn.f32x2 %0, %1, %2, %3;" : "=l"(d) : "l"(a), "l"(b), "l"(c))
#define MUL2(d, a, b) \
    asm("mul.rn.f32x2 %0, %1, %2;" : "=l"(d) : "l"(a), "l"(b))
#define ADD2(d, a, b) \
    asm("add.rn.f32x2 %0, %1, %2;" : "=l"(d) : "l"(a), "l"(b))
#define RCPA(d, s) \
    asm("rcp.approx.f32 %0, %1;" : "=f"(d) : "f"(s))
#define EX2A(d, s) \
    asm("ex2.approx.f32 %0, %1;" : "=f"(d) : "f"(s))

static constexpr float    EPS   = 1e-8f;
static constexpr float    SCALE = 14.4269504088896340736f;  // 10 * log2(e)
static constexpr int      WPB   = 4;                        // warps per block
static constexpr int      SROW  = 36;                       // smem row stride
static constexpr unsigned FULL  = 0xFFFFFFFFu;

__device__ __forceinline__ ull shfl_xor64(ull x, int mask) {
    return __shfl_xor_sync(FULL, x, mask);   // 2 SASS SHFLs
}

struct SKState {
    ull M[4][4];
    ull V[4];
    ull U2[4];
};

// One full row step + col step. Produces u (scalar, own row 4a+b) and the
// v-pair (vx,vy) replicated across duo lanes; refreshes U2. Does NOT do the
// v-allgather (caller decides).
__device__ __forceinline__ void sk_iter_core(SKState& st,
                                             float& u, float& vx, float& vy) {
    // ===== Row step: d = M0 v ; u = 1/d =====
    float D0, D1, D2, D3;
    {
        ull acc;
        MUL2(acc, st.M[0][0], st.V[0]); FMA2(acc, st.M[0][1], st.V[1], acc);
        FMA2(acc, st.M[0][2], st.V[2], acc); FMA2(acc, st.M[0][3], st.V[3], acc);
        float x, y; UNPACK2(x, y, acc); D0 = x + y;
        MUL2(acc, st.M[1][0], st.V[0]); FMA2(acc, st.M[1][1], st.V[1], acc);
        FMA2(acc, st.M[1][2], st.V[2], acc); FMA2(acc, st.M[1][3], st.V[3], acc);
        UNPACK2(x, y, acc); D1 = x + y;
        MUL2(acc, st.M[2][0], st.V[0]); FMA2(acc, st.M[2][1], st.V[1], acc);
        FMA2(acc, st.M[2][2], st.V[2], acc); FMA2(acc, st.M[2][3], st.V[3], acc);
        UNPACK2(x, y, acc); D2 = x + y;
        MUL2(acc, st.M[3][0], st.V[0]); FMA2(acc, st.M[3][1], st.V[1], acc);
        FMA2(acc, st.M[3][2], st.V[2], acc); FMA2(acc, st.M[3][3], st.V[3], acc);
        UNPACK2(x, y, acc); D3 = x + y;
    }
    // xor-slot reduce over b-quad (slot r on lane b holds row 4a+(b^r))
    D0 += __shfl_xor_sync(FULL, D2, 2);
    D1 += __shfl_xor_sync(FULL, D3, 2);
    D0 += __shfl_xor_sync(FULL, D1, 1);          // full d[4a+b]
    RCPA(u, D0);                                 // u = 1/d
    // u allgather into row slots
    {
        float u1 = __shfl_xor_sync(FULL, u, 1);
        float u2 = __shfl_xor_sync(FULL, u, 2);
        float u3 = __shfl_xor_sync(FULL, u, 3);
        PACK2(st.U2[0], u,  u ); PACK2(st.U2[1], u1, u1);
        PACK2(st.U2[2], u2, u2); PACK2(st.U2[3], u3, u3);
    }

    // ===== Col step: c = M0^T u ; v = 1/c  (dual accumulators) =====
    ull C0, C1, C2, C3, B0, B1, B2, B3;
    MUL2(C0, st.M[0][0], st.U2[0]); FMA2(C0, st.M[1][0], st.U2[1], C0);
    MUL2(B0, st.M[2][0], st.U2[2]); FMA2(B0, st.M[3][0], st.U2[3], B0);
    MUL2(C1, st.M[0][1], st.U2[0]); FMA2(C1, st.M[1][1], st.U2[1], C1);
    MUL2(B1, st.M[2][1], st.U2[2]); FMA2(B1, st.M[3][1], st.U2[3], B1);
    MUL2(C2, st.M[0][2], st.U2[0]); FMA2(C2, st.M[1][2], st.U2[1], C2);
    MUL2(B2, st.M[2][2], st.U2[2]); FMA2(B2, st.M[3][2], st.U2[3], B2);
    MUL2(C3, st.M[0][3], st.U2[0]); FMA2(C3, st.M[1][3], st.U2[1], C3);
    MUL2(B3, st.M[2][3], st.U2[2]); FMA2(B3, st.M[3][3], st.U2[3], B3);
    ADD2(C0, C0, B0); ADD2(C1, C1, B1);
    ADD2(C2, C2, B2); ADD2(C3, C3, B3);
    // xor-slot reduce over the 8 a-lanes (pair payloads, duo-complete)
    {
        ull t;
        t = shfl_xor64(C2, 16); ADD2(C0, C0, t);
        t = shfl_xor64(C3, 16); ADD2(C1, C1, t);
        t = shfl_xor64(C1, 8);  ADD2(C0, C0, t);
        t = shfl_xor64(C0, 4);  ADD2(C0, C0, t);  // full pair on duo
    }
    // v-pair update (replicated across duo; no routing selects)
    float cx, cy; UNPACK2(cx, cy, C0);
    RCPA(vx, cx); RCPA(vy, cy);
}

__global__ __launch_bounds__(WPB * 32, 8)
void sinkhorn_kernel(const float* __restrict__ H,
                     float* __restrict__ Out,
                     int nmat) {
    // per-warp: 32x32 padded tile + u[32] + v[32]
    __shared__ __align__(16) float S[WPB][32 * SROW + 64];

    const int lane = threadIdx.x & 31;
    const int wid  = threadIdx.x >> 5;
    const int a    = lane >> 2;      // 0..7 (rows 4a..4a+3)
    const int b    = lane & 3;       // 0..3 (cols 8b..8b+7)
    const int g    = a >> 1;         // 0..3 (own col-pair index in group)
    const int al   = a & 1;          // element within own col pair
    const int g0   = g & 1;          // pair-swap bit
    const int g1   = g >> 1;         // chunk-select bit

    const int m = blockIdx.x * WPB + wid;
    if (m >= nmat) return;           // warp-uniform

    float* s  = S[wid];
    float* su = S[wid] + 32 * SROW;        // u[32]
    float* sv = S[wid] + 32 * SROW + 32;   // v[32]
    const float4* src = reinterpret_cast<const float4*>(H)  + (size_t)m * 256;
    float4*       dst = reinterpret_cast<float4*>(Out)      + (size_t)m * 256;

    ull SC2;  PACK2(SC2, SCALE, SCALE);
    ull ONE2; PACK2(ONE2, 1.0f, 1.0f);

    // ---- Flat load (4 lines/inst), scale+exp+clamp, flat STS.128 ----
#pragma unroll
    for (int k = 0; k < 8; k++) {
        const int f = k * 32 + lane;            // float4 index in matrix
        float4 q = src[f];
        ull p0, p1;
        PACK2(p0, q.x, q.y);
        PACK2(p1, q.z, q.w);
        MUL2(p0, p0, SC2);
        MUL2(p1, p1, SC2);
        float x0, y0, x1, y1;
        UNPACK2(x0, y0, p0); UNPACK2(x1, y1, p1);
        EX2A(x0, x0); EX2A(y0, y0); EX2A(x1, x1); EX2A(y1, y1);
        q.x = fmaxf(x0, EPS); q.y = fmaxf(y0, EPS);
        q.z = fmaxf(x1, EPS); q.w = fmaxf(y1, EPS);
        const int row = f >> 3;                 // 8 float4 per row
        const int ch  = f & 7;
        *reinterpret_cast<float4*>(s + row * SROW + ch * 4) = q;
    }
    __syncwarp();

    // ---- Gather xor-slot registers via conflict-free LDS.128 ----
    // chunk Q = 2b + (g1^T) holds col pairs 2Q (lo) and 2Q+1 (hi);
    // slot 2T is the one whose pair-bit0 == g0.
    SKState st;
#pragma unroll
    for (int r = 0; r < 4; r++) {
        const int R = 4 * a + (b ^ r);
#pragma unroll
        for (int T = 0; T < 2; T++) {
            const int Q = 2 * b + (g1 ^ T);
            const ulonglong2 q =
                *reinterpret_cast<const ulonglong2*>(s + R * SROW + 4 * Q);
            st.M[r][2 * T]     = g0 ? q.y : q.x;
            st.M[r][2 * T + 1] = g0 ? q.x : q.y;
        }
    }

    st.V[0] = ONE2; st.V[1] = ONE2; st.V[2] = ONE2; st.V[3] = ONE2;

    // ---- 9 full iterations (with v-allgather) ----
#pragma unroll 1
    for (int it = 0; it < 9; it++) {
        float u, vx, vy;
        sk_iter_core(st, u, vx, vy);
        // v allgather into col-pair slots
        PACK2(st.V[0], vx, vy);                  // own pair g
        st.V[1] = shfl_xor64(st.V[0], 8);
        st.V[2] = shfl_xor64(st.V[0], 16);
        st.V[3] = shfl_xor64(st.V[0], 24);
    }

    // ---- Peeled final iteration: no v-allgather, write u,v boards ----
    {
        float u, vx, vy;
        sk_iter_core(st, u, vx, vy);
        su[4 * a + b] = u;                       // u[row 4a+b]
        if (al == 0) {                           // one duo lane stores v pair
            sv[8 * b + 2 * g]     = vx;
            sv[8 * b + 2 * g + 1] = vy;
        }
    }
    __syncwarp();

    // ---- Epilogue: out[i][j] = u_i * exp(M0)[i][j] * v_j ----
    // Tile still holds flat exp(M0). Row remap: lane covers rows
    // ro*8 .. ro*8+7 (ro = lane>>3), its 8 u's contiguous in smem
    // (2 broadcast LDS.128). Global stores remain 4x128B lines per inst.
    const int ch = lane & 7;                    // fixed chunk (cols 4ch..4ch+3)
    const int ro = lane >> 3;                   // octet -> row group
    const ulonglong2 vq =
        *reinterpret_cast<const ulonglong2*>(sv + 4 * ch);   // v pairs
    const float4 ua = *reinterpret_cast<const float4*>(su + ro * 8);
    const float4 ub = *reinterpret_cast<const float4*>(su + ro * 8 + 4);
    const float us[8] = { ua.x, ua.y, ua.z, ua.w, ub.x, ub.y, ub.z, ub.w };
#pragma unroll
    for (int k = 0; k < 8; k++) {
        const int row = ro * 8 + k;
        ull ud; PACK2(ud, us[k], us[k]);
        const ulonglong2 mq =
            *reinterpret_cast<const ulonglong2*>(s + row * SROW + ch * 4);
        ull o0, o1;
        MUL2(o0, mq.x, vq.x); MUL2(o0, o0, ud);
        MUL2(o1, mq.y, vq.y); MUL2(o1, o1, ud);
        float4 t;
        UNPACK2(t.x, t.y, o0);
        UNPACK2(t.z, t.w, o1);
        dst[row * 8 + ch] = t;
    }
}

extern "C" void kernel_launch(void* const* d_in, const int* in_sizes, int n_in,
                              void* d_out, int out_size) {
    const float* H   = (const float*)d_in[0];
    float*       out = (float*)d_out;
    const int nmat   = in_sizes[0] / 1024;          // 32*32 per matrix
    const int blocks = (nmat + WPB - 1) / WPB;
    sinkhorn_kernel<<<blocks, WPB * 32>>>(H, out, nmat);
}